// round 12
// baseline (speedup 1.0000x reference)
#include <cuda_runtime.h>
#include <cuda_bf16.h>
#include <cstdint>

#define NN 50000
#define NE 800000
#define NG 256
#define FIN 256
#define HD 64

__device__ float g_q[NN * HD];
__device__ float g_k[NN * HD];
__device__ float g_v[NN * HD];
__device__ float g_ex[NE];
__device__ float g_den[NG];
__device__ float g_inv[NN];
// W transposed: [n=192][k=256], bf16 hi/lo split (rows 0-63 Q, 64-127 K, 128-191 V)
__device__ __nv_bfloat16 g_wth[192 * 256];
__device__ __nv_bfloat16 g_wtl[192 * 256];

// ---- GEMM smem: B resident [64][256] hi/lo + A double-buffered [128][32] ----
#define SMB_HI 0
#define SMB_LO 32768
#define SMA    65536
#define ABUF   20480            // per A buffer: hi 10240 + lo 10240 (stride 80)
#define A_LO   10240
#define SM_TOT (65536 + 2 * ABUF)   // 106496 B = 104 KB

__device__ __forceinline__ uint32_t smem_u32(const void* p) {
    uint32_t a;
    asm("{ .reg .u64 t; cvta.to.shared.u64 t, %1; cvt.u32.u64 %0, t; }"
        : "=r"(a) : "l"(p));
    return a;
}
// B layout: row stride 512B, 16B unit u xor-swizzled for conflict-free ldsm
__device__ __forceinline__ uint32_t off_b(uint32_t n, uint32_t u) {
    return n * 512 + ((u * 16) ^ ((n & 7) << 4));
}
__device__ __forceinline__ void ldsm_x4(uint32_t* r, uint32_t addr) {
    asm volatile("ldmatrix.sync.aligned.m8n8.x4.shared.b16 {%0,%1,%2,%3}, [%4];"
                 : "=r"(r[0]), "=r"(r[1]), "=r"(r[2]), "=r"(r[3]) : "r"(addr));
}
__device__ __forceinline__ void mma_bf16(float* c, const uint32_t* a,
                                         const uint32_t* b) {
    asm volatile(
        "mma.sync.aligned.m16n8k16.row.col.f32.bf16.bf16.f32 "
        "{%0,%1,%2,%3}, {%4,%5,%6,%7}, {%8,%9}, {%0,%1,%2,%3};"
        : "+f"(c[0]), "+f"(c[1]), "+f"(c[2]), "+f"(c[3])
        : "r"(a[0]), "r"(a[1]), "r"(a[2]), "r"(a[3]), "r"(b[0]), "r"(b[1]));
}
__device__ __forceinline__ uint32_t pack_bf2(float x, float y) {
    __nv_bfloat162 h = {__float2bfloat16(x), __float2bfloat16(y)};
    return *(uint32_t*)&h;
}
__device__ __forceinline__ void cp16(uint32_t dst, const void* src) {
    asm volatile("cp.async.cg.shared.global [%0], [%1], 16;"
                 :: "r"(dst), "l"(__cvta_generic_to_global(src)) : "memory");
}
#define CP_COMMIT() asm volatile("cp.async.commit_group;" ::: "memory")
#define CP_WAIT0()  asm volatile("cp.async.wait_group 0;" ::: "memory")

// ---------------------------------------------------------------------------
// W pre-transpose hi/lo. Block 0 of the hi kernel also zeroes g_den.
// ---------------------------------------------------------------------------
__global__ __launch_bounds__(256) void wt_build_h(
    const float* __restrict__ Wq, const float* __restrict__ Wk,
    const float* __restrict__ Wv)
{
    int n = blockIdx.x;
    int k = threadIdx.x;
    if (n == 0) g_den[k] = 0.f;
    const float* W = (n < 64) ? Wq : (n < 128 ? Wk : Wv);
    float w = W[(size_t)k * HD + (n & 63)];
    g_wth[n * FIN + k] = __float2bfloat16(w);
}
__global__ __launch_bounds__(256) void wt_build_l(
    const float* __restrict__ Wq, const float* __restrict__ Wk,
    const float* __restrict__ Wv)
{
    int n = blockIdx.x;
    int k = threadIdx.x;
    const float* W = (n < 64) ? Wq : (n < 128 ? Wk : Wv);
    float w = W[(size_t)k * HD + (n & 63)];
    __nv_bfloat16 h = __float2bfloat16(w);
    g_wtl[n * FIN + k] = __float2bfloat16(w - __bfloat162float(h));
}

// ---------------------------------------------------------------------------
// QKV-split GEMM on HMMA bf16x3. grid (3, 391): blockIdx.x selects {Q,K,V},
// blockIdx.y the 128-row tile. B (64 x 256 hi/lo) is smem-RESIDENT (staged
// once via cp.async); A is double-buffered in K=32 chunks with register
// prefetch overlapped with compute. 8 warps: 4M x 2N; per warp 2mt x 4nt,
// 32 acc regs. 2 CTAs per SM.
// ---------------------------------------------------------------------------
__global__ __launch_bounds__(256, 2) void qkv_gemm_hmma(
    const float* __restrict__ x,
    const float* __restrict__ bq, const float* __restrict__ bk,
    const float* __restrict__ bv)
{
    extern __shared__ char smem[];
    const uint32_t sb = smem_u32(smem);
    const int tid = threadIdx.x;
    const int wid = tid >> 5;
    const int lane = tid & 31;
    const int m_warp = wid & 3;       // 4 M groups of 32 rows
    const int n_warp = wid >> 2;      // 2 N groups of 32 cols
    const int sel  = blockIdx.x;      // 0=Q, 1=K, 2=V
    const int row0 = blockIdx.y * 128;

    float acc[2][4][4];
#pragma unroll
    for (int i = 0; i < 2; i++)
#pragma unroll
        for (int j = 0; j < 4; j++)
#pragma unroll
            for (int t = 0; t < 4; t++) acc[i][j][t] = 0.f;

    const int lm_r = lane & 15;
    const int lm_h = lane >> 4;
    const int ar  = tid >> 1;         // A row (0..127)
    const int ah2 = tid & 1;          // half row (16 floats each)

    float4 pa[4];                     // A prefetch registers

    auto load_A = [&](int c) {
        int grow = row0 + ar;
        if (grow < NN) {
            const float* src = &x[(size_t)grow * FIN + c * 32 + ah2 * 16];
#pragma unroll
            for (int l = 0; l < 4; l++) pa[l] = *(const float4*)(src + l * 4);
        } else {
#pragma unroll
            for (int l = 0; l < 4; l++) pa[l] = make_float4(0.f, 0.f, 0.f, 0.f);
        }
    };
    auto sts_A = [&](int buf) {
        uint32_t hi[8], lo[8];
#pragma unroll
        for (int l = 0; l < 4; l++) {
            float a = pa[l].x, b = pa[l].y, cc = pa[l].z, dd = pa[l].w;
            __nv_bfloat16 ha = __float2bfloat16(a), hb = __float2bfloat16(b);
            __nv_bfloat16 hc = __float2bfloat16(cc), hd = __float2bfloat16(dd);
            hi[l * 2]     = pack_bf2(a, b);
            hi[l * 2 + 1] = pack_bf2(cc, dd);
            lo[l * 2]     = pack_bf2(a - __bfloat162float(ha),
                                     b - __bfloat162float(hb));
            lo[l * 2 + 1] = pack_bf2(cc - __bfloat162float(hc),
                                     dd - __bfloat162float(hd));
        }
        uint32_t abase = sb + SMA + buf * ABUF + ar * 80 + ah2 * 32;
        *(uint4*)(smem + (abase - sb))            = make_uint4(hi[0], hi[1], hi[2], hi[3]);
        *(uint4*)(smem + (abase - sb) + 16)       = make_uint4(hi[4], hi[5], hi[6], hi[7]);
        *(uint4*)(smem + (abase - sb) + A_LO)     = make_uint4(lo[0], lo[1], lo[2], lo[3]);
        *(uint4*)(smem + (abase - sb) + A_LO + 16) = make_uint4(lo[4], lo[5], lo[6], lo[7]);
    };
    auto compute = [&](int c) {
        const int buf = c & 1;
        const uint32_t ah_base = sb + SMA + buf * ABUF;
        const uint32_t al_base = ah_base + A_LO;
#pragma unroll
        for (int ks = 0; ks < 2; ks++) {
            const int kb = ks * 2 + lm_h;        // A unit (0..3)
            const int bu = c * 4 + kb;           // B unit (0..31)
            uint32_t ah[2][4], al[2][4];
#pragma unroll
            for (int mt = 0; mt < 2; mt++) {
                int r = m_warp * 32 + mt * 16 + lm_r;
                ldsm_x4(ah[mt], ah_base + r * 80 + kb * 16);
                ldsm_x4(al[mt], al_base + r * 80 + kb * 16);
            }
#pragma unroll
            for (int p = 0; p < 2; p++) {        // pairs of n-tiles
                int n = n_warp * 32 + p * 16 + lm_r;
                uint32_t th[4], tl[4];
                ldsm_x4(th, sb + SMB_HI + off_b(n, bu));
                ldsm_x4(tl, sb + SMB_LO + off_b(n, bu));
                uint32_t bh0[2] = {th[0], th[2]}, bh1[2] = {th[1], th[3]};
                uint32_t bl0[2] = {tl[0], tl[2]}, bl1[2] = {tl[1], tl[3]};
#pragma unroll
                for (int mt = 0; mt < 2; mt++) {
                    mma_bf16(acc[mt][p * 2], ah[mt], bh0);
                    mma_bf16(acc[mt][p * 2], ah[mt], bl0);
                    mma_bf16(acc[mt][p * 2], al[mt], bh0);
                    mma_bf16(acc[mt][p * 2 + 1], ah[mt], bh1);
                    mma_bf16(acc[mt][p * 2 + 1], ah[mt], bl1);
                    mma_bf16(acc[mt][p * 2 + 1], al[mt], bh1);
                }
            }
        }
    };

    // ---- prologue: B resident via cp.async; A chunk 0 via LDG+cvt ----
    const __nv_bfloat16* bh_src = g_wth + (size_t)(sel * 64) * FIN;
    const __nv_bfloat16* bl_src = g_wtl + (size_t)(sel * 64) * FIN;
#pragma unroll
    for (int it = 0; it < 8; it++) {
        int idx = tid + it * 256;     // 2048 units: n = idx>>5, u = idx&31
        int n = idx >> 5, u = idx & 31;
        cp16(sb + SMB_HI + off_b(n, u), bh_src + n * FIN + u * 8);
        cp16(sb + SMB_LO + off_b(n, u), bl_src + n * FIN + u * 8);
    }
    CP_COMMIT();
    load_A(0);
    sts_A(0);
    CP_WAIT0();
    __syncthreads();

    // ---- main loop: 8 chunks of K=32; A(c+1) prefetch overlaps compute(c) ----
#pragma unroll
    for (int c = 0; c < 8; c++) {
        if (c < 7) load_A(c + 1);
        compute(c);
        if (c < 7) sts_A((c + 1) & 1);
        __syncthreads();
    }

    // ---- epilogue ----
    const float* bias = sel == 0 ? bq : (sel == 1 ? bk : bv);
    float* out = sel == 0 ? g_q : (sel == 1 ? g_k : g_v);
    const int r0 = lane >> 2;
    const int cp = (lane & 3) * 2;
#pragma unroll
    for (int mt = 0; mt < 2; mt++) {
        int gr = row0 + m_warp * 32 + mt * 16 + r0;
#pragma unroll
        for (int nt = 0; nt < 4; nt++) {
            int ci = n_warp * 32 + nt * 8 + cp;
            float b0 = bias[ci], b1 = bias[ci + 1];
            if (gr < NN) {
                float2 st = make_float2(acc[mt][nt][0] + b0, acc[mt][nt][1] + b1);
                *(float2*)&out[(size_t)gr * HD + ci] = st;
            }
            if (gr + 8 < NN) {
                float2 st = make_float2(acc[mt][nt][2] + b0, acc[mt][nt][3] + b1);
                *(float2*)&out[(size_t)(gr + 8) * HD + ci] = st;
            }
        }
    }
}

// ---------------------------------------------------------------------------
// Pass 1: ex[e] = exp(dot(k[src], q[dest]) / 8); denominator via shared bins.
// ---------------------------------------------------------------------------
__global__ __launch_bounds__(512) void edge_pass1(
    const int* __restrict__ ei, const int* __restrict__ batch)
{
    __shared__ float sden[NG];
    const int tid = threadIdx.x;
    if (tid < NG) sden[tid] = 0.f;
    __syncthreads();

    const int lane = tid & 31;
    const int sub = lane >> 3;
    const int sl  = lane & 7;
    const int w = blockIdx.x * 16 + (tid >> 5);
    const int stride = gridDim.x * 16 * 4;

    for (int e0 = w * 4; e0 < NE; e0 += stride) {
        int e = e0 + sub;
        float p = 0.f;
        int s = 0;
        if (e < NE) {
            s = __ldg(&ei[e]);
            int d = __ldg(&ei[NE + e]);
            const float* kr = &g_k[s * HD + sl * 8];
            const float* qr = &g_q[d * HD + sl * 8];
            float4 k0 = *(const float4*)kr;
            float4 k1 = *(const float4*)(kr + 4);
            float4 q0 = *(const float4*)qr;
            float4 q1 = *(const float4*)(qr + 4);
            p = k0.x * q0.x + k0.y * q0.y + k0.z * q0.z + k0.w * q0.w
              + k1.x * q1.x + k1.y * q1.y + k1.z * q1.z + k1.w * q1.w;
        }
#pragma unroll
        for (int o = 4; o > 0; o >>= 1)
            p += __shfl_xor_sync(0xffffffffu, p, o);
        if (sl == 0 && e < NE) {
            float ex = __expf(p * 0.125f);
            g_ex[e] = ex;
            atomicAdd(&sden[__ldg(&batch[s])], ex);
        }
    }
    __syncthreads();
    if (tid < NG) {
        float v = sden[tid];
        if (v != 0.f) atomicAdd(&g_den[tid], v);
    }
}

// ---------------------------------------------------------------------------
__global__ __launch_bounds__(256) void node_inv(const int* __restrict__ batch)
{
    int n = blockIdx.x * 256 + threadIdx.x;
    if (n < NN)
        g_inv[n] = __frcp_rn(g_den[__ldg(&batch[n])] + 1e-6f);
}

// ---------------------------------------------------------------------------
// Pass 2: out[dest] += v[src] * (ex[e] * inv[src]).
// ---------------------------------------------------------------------------
__global__ __launch_bounds__(256) void edge_pass2(
    const int* __restrict__ ei, float* __restrict__ out)
{
    const int lane = threadIdx.x & 31;
    const int half = lane >> 4;
    const int hl   = lane & 15;
    const int e = (blockIdx.x * 8 + (threadIdx.x >> 5)) * 2 + half;
    if (e >= NE) return;

    int s = __ldg(&ei[e]);
    int d = __ldg(&ei[NE + e]);

    float a = 0.f;
    if (hl == 0) a = g_ex[e] * g_inv[s];
    a = __shfl_sync(0xffffffffu, a, half << 4);

    float4 vv = *(const float4*)&g_v[s * HD + hl * 4];
    float* dst = &out[d * HD + hl * 4];
    asm volatile("red.global.add.v4.f32 [%0], {%1, %2, %3, %4};"
                 :: "l"(dst), "f"(vv.x * a), "f"(vv.y * a),
                    "f"(vv.z * a), "f"(vv.w * a)
                 : "memory");
}

// ---------------------------------------------------------------------------
extern "C" void kernel_launch(void* const* d_in, const int* in_sizes, int n_in,
                              void* d_out, int out_size)
{
    const float* x     = (const float*)d_in[0];
    const float* Wq    = (const float*)d_in[1];
    const float* bq    = (const float*)d_in[2];
    const float* Wk    = (const float*)d_in[3];
    const float* bk    = (const float*)d_in[4];
    const float* Wv    = (const float*)d_in[5];
    const float* bv    = (const float*)d_in[6];
    const int*   ei    = (const int*)d_in[7];    // int32 (JAX x64 disabled)
    const int*   batch = (const int*)d_in[8];
    float* out = (float*)d_out;

    cudaFuncSetAttribute(qkv_gemm_hmma,
                         cudaFuncAttributeMaxDynamicSharedMemorySize, SM_TOT);

    // Launch order: ncu (-s 5) profiles the GEMM.
    cudaMemsetAsync(d_out, 0, (size_t)out_size * sizeof(float));   // 1
    wt_build_h<<<192, 256>>>(Wq, Wk, Wv);                          // 2 (+zero g_den)
    wt_build_l<<<192, 256>>>(Wq, Wk, Wv);                          // 3
    node_inv<<<1, 1>>>(batch);                                     // 4 (pad)
    dim3 gg(3, (NN + 127) / 128);
    qkv_gemm_hmma<<<gg, 256, SM_TOT>>>(x, bq, bk, bv);             // 5 <- ncu
    edge_pass1<<<592, 512>>>(ei, batch);                           // 6
    node_inv<<<(NN + 255) / 256, 256>>>(batch);                    // 7
    edge_pass2<<<NE / 16, 256>>>(ei, out);                         // 8
}